// round 11
// baseline (speedup 1.0000x reference)
#include <cuda_runtime.h>
#include <cuda_fp16.h>
#include <cstdint>

#define BATCH 16
#define LQ    2048
#define LK    2048
#define DDIM  1024

// ---------------------------------------------------------------------------
// Scratch (device globals — sanctioned no-alloc scratch)
// ---------------------------------------------------------------------------
__device__ __half g_Qh[(size_t)BATCH * LQ * DDIM];
__device__ __half g_Ql[(size_t)BATCH * LQ * DDIM];
__device__ __half g_Vh[(size_t)BATCH * LK * DDIM];
__device__ __half g_Vl[(size_t)BATCH * LK * DDIM];
__device__ __half g_VTh[(size_t)BATCH * DDIM * LK];
__device__ __half g_Ph[(size_t)BATCH * LQ * LK];

// ---------------------------------------------------------------------------
// PTX helpers (plain sm_80+ PTX only)
// ---------------------------------------------------------------------------
static __device__ __forceinline__ uint32_t smem_u32(const void* p) {
    uint32_t a;
    asm("{ .reg .u64 t; cvta.to.shared.u64 t, %1; cvt.u32.u64 %0, t; }"
        : "=r"(a) : "l"(p));
    return a;
}
static __device__ __forceinline__ void cpa16(uint32_t dst, const void* src) {
    asm volatile("cp.async.cg.shared.global [%0], [%1], 16;"
                 :: "r"(dst), "l"(src) : "memory");
}
static __device__ __forceinline__ void cp_commit() {
    asm volatile("cp.async.commit_group;" ::: "memory");
}
template <int N> static __device__ __forceinline__ void cp_wait() {
    asm volatile("cp.async.wait_group %0;" :: "n"(N) : "memory");
}
static __device__ __forceinline__ void ldm4(uint32_t* r, uint32_t addr) {
    asm volatile("ldmatrix.sync.aligned.m8n8.x4.shared.b16 {%0,%1,%2,%3}, [%4];"
                 : "=r"(r[0]), "=r"(r[1]), "=r"(r[2]), "=r"(r[3]) : "r"(addr));
}
static __device__ __forceinline__ void mma16816(float* c, const uint32_t* a,
                                                const uint32_t* b) {
    asm volatile(
        "mma.sync.aligned.m16n8k16.row.col.f32.f16.f16.f32 "
        "{%0,%1,%2,%3}, {%4,%5,%6,%7}, {%8,%9}, {%0,%1,%2,%3};"
        : "+f"(c[0]), "+f"(c[1]), "+f"(c[2]), "+f"(c[3])
        : "r"(a[0]), "r"(a[1]), "r"(a[2]), "r"(a[3]), "r"(b[0]), "r"(b[1]));
}
static __device__ __forceinline__ uint32_t pk_h2(float a, float b) {
    __half2 t = __floats2half2_rn(a, b);
    return *reinterpret_cast<uint32_t*>(&t);
}

// ---------------------------------------------------------------------------
// fp16-split HMMA GEMM, templated on plane counts:
//   <2,2>: C = (Ah+Al)·(Bh+Bl)^T, 3 MMAs (hh, hl, lh)   [GEMM1]
//   <1,1>: C =  Ah    · Bh^T,     1 MMA                  [GEMM2]
// CTA 128x128, 8 warps (2x4), warp tile 64x32, KT=32, 2-stage cp.async.
// Per iter: cp_wait<0> -> __syncthreads -> load(t+1) -> compute(t).
//   (wait BEFORE barrier — the R5/R9 lesson)
// MMA issue order is plane-major: all 16 (mf,nf) of hh, then hl, then lh —
// each accumulator reused every 16 MMAs, hiding the HMMA RAW latency.
// 2 CTAs/SM. smem rows padded to 80B -> conflict-free ldmatrix (R3-verified).
// ---------------------------------------------------------------------------
#define KT          32
#define ROWB        80                   /* bytes per smem row (32 fp16 + pad) */
#define MAT_BYTES   (128 * ROWB)         /* 10240 */
#define NSTAGE      2

template <int APLANES, int BPLANES>
__global__ __launch_bounds__(256, 2)
void gemm_hmma(const __half* __restrict__ pAh, const __half* __restrict__ pAl,
               const __half* __restrict__ pBh, const __half* __restrict__ pBl,
               float* __restrict__ pC,
               int K, int ldc, long sA, long sB, long sC)
{
    constexpr int NMAT = APLANES + BPLANES;
    constexpr uint32_t STAGE = NMAT * MAT_BYTES;

    extern __shared__ __align__(128) char smem[];
    const uint32_t sb = smem_u32(smem);

    const int tid  = threadIdx.x;
    const int wid  = tid >> 5;
    const int lane = tid & 31;
    const int wr   = wid & 1;        // warp row (0..1) -> 64 rows each
    const int wc   = wid >> 1;       // warp col (0..3) -> 32 cols each

    const int brow = blockIdx.y << 7;
    const int bcol = blockIdx.x << 7;
    const int bz   = blockIdx.z;

    const __half* mats[NMAT];
    mats[0] = pAh + (size_t)bz * sA + (size_t)brow * K;
    if (APLANES == 2) mats[1] = pAl + (size_t)bz * sA + (size_t)brow * K;
    mats[APLANES] = pBh + (size_t)bz * sB + (size_t)bcol * K;
    if (BPLANES == 2) mats[APLANES + 1] = pBl + (size_t)bz * sB + (size_t)bcol * K;

    // loader: per matrix, 512 16B-chunks (128 rows x 4); 2 chunks per thread
    auto load_stage = [&](int t) {
        const int koff = t * KT;
        const uint32_t stage = sb + (t & 1) * STAGE;
#pragma unroll
        for (int m = 0; m < NMAT; ++m) {
#pragma unroll
            for (int i = 0; i < 2; ++i) {
                const int j   = i * 256 + tid;      // 0..511
                const int row = j >> 2;
                const int c16 = j & 3;
                cpa16(stage + m * MAT_BYTES + row * ROWB + c16 * 16,
                      mats[m] + (size_t)row * K + koff + c16 * 8);
            }
        }
        cp_commit();
    };

    float acc[4][4][4];
#pragma unroll
    for (int i = 0; i < 4; ++i)
#pragma unroll
        for (int j = 0; j < 4; ++j)
#pragma unroll
            for (int k = 0; k < 4; ++k) acc[i][j][k] = 0.f;

    const int NT = K / KT;
    load_stage(0);

    // ldmatrix lane offsets (bytes), pitch ROWB (mapping verified in R3)
    const int l7 = lane & 7, l3 = (lane >> 3) & 1, l4 = lane >> 4;
    const uint32_t a_off = (uint32_t)((wr * 64 + l3 * 8 + l7) * ROWB + l4 * 16);
    const uint32_t b_off = (uint32_t)((wc * 32 + l4 * 8 + l7) * ROWB + l3 * 16)
                           + (uint32_t)APLANES * MAT_BYTES;

    for (int t = 0; t < NT; ++t) {
        // 1) this thread's tile-t load complete (only pending group)
        cp_wait<0>();
        // 2) publish ALL threads' tile-t data; buffer (t+1)&1 reads done
        __syncthreads();
        // 3) prefetch tile t+1 (overlaps with compute below)
        if (t + 1 < NT) load_stage(t + 1);

        const uint32_t stage = sb + (t & 1) * STAGE;
#pragma unroll
        for (int ks = 0; ks < 2; ++ks) {
            const uint32_t kb = (uint32_t)(ks * 32);

            // ---- load ALL fragments for this ks first ----
            uint32_t bh[8], bl[8];
#pragma unroll
            for (int g = 0; g < 2; ++g) {
                const uint32_t ba = stage + b_off + g * 16 * ROWB + kb;
                ldm4(bh + 4 * g, ba);
                if (BPLANES == 2) ldm4(bl + 4 * g, ba + MAT_BYTES);
            }
            uint32_t ah[16], al[16];
#pragma unroll
            for (int mf = 0; mf < 4; ++mf) {
                const uint32_t aa = stage + a_off + mf * 16 * ROWB + kb;
                ldm4(ah + 4 * mf, aa);
                if (APLANES == 2) ldm4(al + 4 * mf, aa + MAT_BYTES);
            }

            // ---- plane-major MMA issue: each acc reused every 16 MMAs ----
#pragma unroll
            for (int mf = 0; mf < 4; ++mf)
#pragma unroll
                for (int nf = 0; nf < 4; ++nf)
                    mma16816(acc[mf][nf], ah + 4 * mf, bh + 2 * nf);
            if (BPLANES == 2) {
#pragma unroll
                for (int mf = 0; mf < 4; ++mf)
#pragma unroll
                    for (int nf = 0; nf < 4; ++nf)
                        mma16816(acc[mf][nf], ah + 4 * mf, bl + 2 * nf);
            }
            if (APLANES == 2) {
#pragma unroll
                for (int mf = 0; mf < 4; ++mf)
#pragma unroll
                    for (int nf = 0; nf < 4; ++nf)
                        mma16816(acc[mf][nf], al + 4 * mf, bh + 2 * nf);
            }
        }
    }

    // epilogue: direct gmem stores, float2 per fragment half
    const int q  = lane >> 2;
    const int tq = lane & 3;
    float* C = pC + (size_t)bz * sC;
#pragma unroll
    for (int mf = 0; mf < 4; ++mf) {
        const int m0 = brow + wr * 64 + mf * 16 + q;
#pragma unroll
        for (int nf = 0; nf < 4; ++nf) {
            const int n = bcol + wc * 32 + nf * 8 + 2 * tq;
            *(float2*)(C + (size_t)m0 * ldc + n) =
                make_float2(acc[mf][nf][0], acc[mf][nf][1]);
            *(float2*)(C + (size_t)(m0 + 8) * ldc + n) =
                make_float2(acc[mf][nf][2], acc[mf][nf][3]);
        }
    }
}

// ---------------------------------------------------------------------------
// Q -> (Qh, Ql) elementwise fp16 hi/lo split, 8 elems/thread
// ---------------------------------------------------------------------------
__global__ __launch_bounds__(256)
void cvt_hilo8(const float* __restrict__ x,
               __half* __restrict__ h, __half* __restrict__ l)
{
    const size_t i = ((size_t)blockIdx.x * blockDim.x + threadIdx.x) * 8;
    const float4 a = *(const float4*)(x + i);
    const float4 b = *(const float4*)(x + i + 4);
    const float v[8] = {a.x, a.y, a.z, a.w, b.x, b.y, b.z, b.w};
    float hf[8], lf[8];
#pragma unroll
    for (int j = 0; j < 8; ++j) {
        hf[j] = __half2float(__float2half_rn(v[j]));
        lf[j] = v[j] - hf[j];
    }
    *(uint4*)(h + i) = make_uint4(pk_h2(hf[0], hf[1]), pk_h2(hf[2], hf[3]),
                                  pk_h2(hf[4], hf[5]), pk_h2(hf[6], hf[7]));
    *(uint4*)(l + i) = make_uint4(pk_h2(lf[0], lf[1]), pk_h2(lf[2], lf[3]),
                                  pk_h2(lf[4], lf[5]), pk_h2(lf[6], lf[7]));
}

// ---------------------------------------------------------------------------
// V -> (Vh, Vl) and transposed hi plane (VTh), fp16. 32x32 tiles, block (32,8).
// ---------------------------------------------------------------------------
__global__ __launch_bounds__(256)
void cvtV(const float* __restrict__ V,
          __half* __restrict__ Vh, __half* __restrict__ Vl,
          __half* __restrict__ VTh)
{
    __shared__ float ts[32][33];
    const int bz = blockIdx.z;
    const float* Vb = V + (size_t)bz * LK * DDIM;
    const int x  = blockIdx.x * 32 + threadIdx.x;   // d
    const int y0 = blockIdx.y * 32 + threadIdx.y;   // k base

#pragma unroll
    for (int j = 0; j < 4; ++j) {
        const int k = y0 + j * 8;
        const float v = Vb[(size_t)k * DDIM + x];
        ts[threadIdx.y + j * 8][threadIdx.x] = v;
        const __half hb = __float2half_rn(v);
        const float hfv = __half2float(hb);
        const size_t o = (size_t)bz * LK * DDIM + (size_t)k * DDIM + x;
        Vh[o] = hb;
        Vl[o] = __float2half_rn(v - hfv);
    }
    __syncthreads();
#pragma unroll
    for (int j = 0; j < 4; ++j) {
        const int d = blockIdx.x * 32 + threadIdx.y + j * 8;
        const int k = blockIdx.y * 32 + threadIdx.x;
        const float v = ts[threadIdx.x][threadIdx.y + j * 8];
        const size_t o = (size_t)bz * DDIM * LK + (size_t)d * LK + k;
        VTh[o] = __float2half_rn(v);
    }
}

// ---------------------------------------------------------------------------
// Row softmax in place + emit fp16 plane of the result (single plane).
// ---------------------------------------------------------------------------
__global__ __launch_bounds__(256)
void softmax_rows(float* __restrict__ S, __half* __restrict__ Ph)
{
    __shared__ float redmax[8];
    __shared__ float redsum[8];

    const size_t rowbase = (size_t)blockIdx.x * LK;
    float* p = S + rowbase;
    const int tid  = threadIdx.x;
    const int lane = tid & 31;
    const int warp = tid >> 5;

    const float4 v0 = *(const float4*)(p + tid * 8);
    const float4 v1 = *(const float4*)(p + tid * 8 + 4);

    float m = fmaxf(fmaxf(fmaxf(v0.x, v0.y), fmaxf(v0.z, v0.w)),
                    fmaxf(fmaxf(v1.x, v1.y), fmaxf(v1.z, v1.w)));
#pragma unroll
    for (int o = 16; o > 0; o >>= 1)
        m = fmaxf(m, __shfl_xor_sync(0xffffffffu, m, o));
    if (lane == 0) redmax[warp] = m;
    __syncthreads();
    float bm = redmax[0];
#pragma unroll
    for (int w = 1; w < 8; ++w) bm = fmaxf(bm, redmax[w]);

    float e[8];
    e[0] = __expf(v0.x - bm); e[1] = __expf(v0.y - bm);
    e[2] = __expf(v0.z - bm); e[3] = __expf(v0.w - bm);
    e[4] = __expf(v1.x - bm); e[5] = __expf(v1.y - bm);
    e[6] = __expf(v1.z - bm); e[7] = __expf(v1.w - bm);

    float s = ((e[0] + e[1]) + (e[2] + e[3])) + ((e[4] + e[5]) + (e[6] + e[7]));
#pragma unroll
    for (int o = 16; o > 0; o >>= 1)
        s += __shfl_xor_sync(0xffffffffu, s, o);
    if (lane == 0) redsum[warp] = s;
    __syncthreads();
    float total = redsum[0];
#pragma unroll
    for (int w = 1; w < 8; ++w) total += redsum[w];
    const float inv = 1.0f / total;

    float y[8];
#pragma unroll
    for (int j = 0; j < 8; ++j) y[j] = e[j] * inv;

    *(float4*)(p + tid * 8)     = make_float4(y[0], y[1], y[2], y[3]);
    *(float4*)(p + tid * 8 + 4) = make_float4(y[4], y[5], y[6], y[7]);

    const size_t ob = rowbase + (size_t)tid * 8;
    *(uint4*)(Ph + ob) = make_uint4(pk_h2(y[0], y[1]), pk_h2(y[2], y[3]),
                                    pk_h2(y[4], y[5]), pk_h2(y[6], y[7]));
}

// ---------------------------------------------------------------------------
// kernel_launch
// ---------------------------------------------------------------------------
extern "C" void kernel_launch(void* const* d_in, const int* in_sizes, int n_in,
                              void* d_out, int out_size)
{
    const float* Q = (const float*)d_in[0];
    const float* V = (const float*)d_in[1];
    float* ctx  = (float*)d_out;
    float* attn = ctx + (size_t)BATCH * LQ * DDIM;

    void *qh, *ql, *vh, *vl, *vth, *ph;
    cudaGetSymbolAddress(&qh, g_Qh);
    cudaGetSymbolAddress(&ql, g_Ql);
    cudaGetSymbolAddress(&vh, g_Vh);
    cudaGetSymbolAddress(&vl, g_Vl);
    cudaGetSymbolAddress(&vth, g_VTh);
    cudaGetSymbolAddress(&ph, g_Ph);

    cudaFuncSetAttribute(gemm_hmma<2, 2>, cudaFuncAttributeMaxDynamicSharedMemorySize,
                         NSTAGE * 4 * MAT_BYTES);
    cudaFuncSetAttribute(gemm_hmma<1, 1>, cudaFuncAttributeMaxDynamicSharedMemorySize,
                         NSTAGE * 2 * MAT_BYTES);

    // fp16 hi/lo splits
    cvt_hilo8<<<(unsigned)((size_t)BATCH * LQ * DDIM / (256 * 8)), 256>>>(
        Q, (__half*)qh, (__half*)ql);
    cvtV<<<dim3(DDIM / 32, LK / 32, BATCH), dim3(32, 8)>>>(
        V, (__half*)vh, (__half*)vl, (__half*)vth);

    // GEMM1: scores = Q · V^T  (3 MMAs/frag) -> attn buffer
    gemm_hmma<2, 2><<<dim3(LK / 128, LQ / 128, BATCH), 256, NSTAGE * 4 * MAT_BYTES>>>(
        (const __half*)qh, (const __half*)ql,
        (const __half*)vh, (const __half*)vl,
        attn, DDIM, LK,
        (long)LQ * DDIM, (long)LK * DDIM, (long)LQ * LK);

    // softmax over key axis (in place) + fp16 P plane
    softmax_rows<<<BATCH * LQ, 256>>>(attn, (__half*)ph);

    // GEMM2: ctx = Ph · VTh^T  (1 MMA/frag)
    gemm_hmma<1, 1><<<dim3(DDIM / 128, LQ / 128, BATCH), 256, NSTAGE * 2 * MAT_BYTES>>>(
        (const __half*)ph, nullptr,
        (const __half*)vth, nullptr,
        ctx, LK, DDIM,
        (long)LQ * LK, (long)DDIM * LK, (long)LQ * DDIM);
}

// round 12
// speedup vs baseline: 1.0505x; 1.0505x over previous
#include <cuda_runtime.h>
#include <cuda_fp16.h>
#include <cstdint>

#define BATCH 16
#define LQ    2048
#define LK    2048
#define DDIM  1024

// ---------------------------------------------------------------------------
// Scratch (device globals — sanctioned no-alloc scratch)
// ---------------------------------------------------------------------------
__device__ __half g_Qh[(size_t)BATCH * LQ * DDIM];
__device__ __half g_Ql[(size_t)BATCH * LQ * DDIM];
__device__ __half g_Vh[(size_t)BATCH * LK * DDIM];
__device__ __half g_Vl[(size_t)BATCH * LK * DDIM];
__device__ __half g_VTh[(size_t)BATCH * DDIM * LK];
__device__ __half g_Ph[(size_t)BATCH * LQ * LK];

// ---------------------------------------------------------------------------
// PTX helpers (plain sm_80+ PTX only)
// ---------------------------------------------------------------------------
static __device__ __forceinline__ uint32_t smem_u32(const void* p) {
    uint32_t a;
    asm("{ .reg .u64 t; cvta.to.shared.u64 t, %1; cvt.u32.u64 %0, t; }"
        : "=r"(a) : "l"(p));
    return a;
}
static __device__ __forceinline__ void cpa16(uint32_t dst, const void* src) {
    asm volatile("cp.async.cg.shared.global [%0], [%1], 16;"
                 :: "r"(dst), "l"(src) : "memory");
}
static __device__ __forceinline__ void cp_commit() {
    asm volatile("cp.async.commit_group;" ::: "memory");
}
template <int N> static __device__ __forceinline__ void cp_wait() {
    asm volatile("cp.async.wait_group %0;" :: "n"(N) : "memory");
}
static __device__ __forceinline__ void ldm4(uint32_t* r, uint32_t addr) {
    asm volatile("ldmatrix.sync.aligned.m8n8.x4.shared.b16 {%0,%1,%2,%3}, [%4];"
                 : "=r"(r[0]), "=r"(r[1]), "=r"(r[2]), "=r"(r[3]) : "r"(addr));
}
static __device__ __forceinline__ void mma16816(float* c, const uint32_t* a,
                                                const uint32_t* b) {
    asm volatile(
        "mma.sync.aligned.m16n8k16.row.col.f32.f16.f16.f32 "
        "{%0,%1,%2,%3}, {%4,%5,%6,%7}, {%8,%9}, {%0,%1,%2,%3};"
        : "+f"(c[0]), "+f"(c[1]), "+f"(c[2]), "+f"(c[3])
        : "r"(a[0]), "r"(a[1]), "r"(a[2]), "r"(a[3]), "r"(b[0]), "r"(b[1]));
}
static __device__ __forceinline__ uint32_t pk_h2(float a, float b) {
    __half2 t = __floats2half2_rn(a, b);
    return *reinterpret_cast<uint32_t*>(&t);
}

// ---------------------------------------------------------------------------
// fp16-split HMMA GEMM, templated on plane counts + k-tile:
//   <2,2,32,80>:  C = (Ah+Al)·(Bh+Bl)^T, 3 MMAs (hh, hl, lh)   [GEMM1]
//   <1,1,64,144>: C =  Ah    · Bh^T,     1 MMA, half the syncs  [GEMM2]
// CTA 128x128, 8 warps (2x4), warp tile 64x32, 2-stage cp.async.
// Per iter: cp_wait<0> -> __syncthreads -> load(t+1) -> compute(t).
//   (wait BEFORE barrier — the R5/R9 lesson)
// 2 CTAs/SM both configs. Row pitches 80B / 144B are conflict-free for
// ldmatrix (8-row bank starts all distinct mod 32 words).
// ---------------------------------------------------------------------------
#define NSTAGE 2

template <int APLANES, int BPLANES, int KTILE, int RB>
__global__ __launch_bounds__(256, 2)
void gemm_hmma(const __half* __restrict__ pAh, const __half* __restrict__ pAl,
               const __half* __restrict__ pBh, const __half* __restrict__ pBl,
               float* __restrict__ pC,
               int K, int ldc, long sA, long sB, long sC)
{
    constexpr int NMAT = APLANES + BPLANES;
    constexpr uint32_t MB    = 128 * RB;        // bytes per matrix per stage
    constexpr uint32_t STAGE = NMAT * MB;
    constexpr int CPR = KTILE / 8;              // 16B chunks per row
    constexpr int LI  = KTILE / 16;             // loader iters per matrix
    constexpr int KS  = KTILE / 16;             // k16 sub-steps per tile

    extern __shared__ __align__(128) char smem[];
    const uint32_t sb = smem_u32(smem);

    const int tid  = threadIdx.x;
    const int wid  = tid >> 5;
    const int lane = tid & 31;
    const int wr   = wid & 1;        // warp row (0..1) -> 64 rows each
    const int wc   = wid >> 1;       // warp col (0..3) -> 32 cols each

    const int brow = blockIdx.y << 7;
    const int bcol = blockIdx.x << 7;
    const int bz   = blockIdx.z;

    const __half* mats[NMAT];
    mats[0] = pAh + (size_t)bz * sA + (size_t)brow * K;
    if (APLANES == 2) mats[1] = pAl + (size_t)bz * sA + (size_t)brow * K;
    mats[APLANES] = pBh + (size_t)bz * sB + (size_t)bcol * K;
    if (BPLANES == 2) mats[APLANES + 1] = pBl + (size_t)bz * sB + (size_t)bcol * K;

    // loader: per matrix, 128 rows x CPR 16B-chunks; LI chunks per thread
    auto load_stage = [&](int t) {
        const int koff = t * KTILE;
        const uint32_t stage = sb + (t & 1) * STAGE;
#pragma unroll
        for (int m = 0; m < NMAT; ++m) {
#pragma unroll
            for (int i = 0; i < LI; ++i) {
                const int j   = i * 256 + tid;
                const int row = j / CPR;
                const int c16 = j % CPR;
                cpa16(stage + m * MB + row * RB + c16 * 16,
                      mats[m] + (size_t)row * K + koff + c16 * 8);
            }
        }
        cp_commit();
    };

    float acc[4][4][4];
#pragma unroll
    for (int i = 0; i < 4; ++i)
#pragma unroll
        for (int j = 0; j < 4; ++j)
#pragma unroll
            for (int k = 0; k < 4; ++k) acc[i][j][k] = 0.f;

    const int NT = K / KTILE;
    load_stage(0);

    // ldmatrix lane offsets (bytes), pitch RB (mapping verified in R3)
    const int l7 = lane & 7, l3 = (lane >> 3) & 1, l4 = lane >> 4;
    const uint32_t a_off = (uint32_t)((wr * 64 + l3 * 8 + l7) * RB + l4 * 16);
    const uint32_t b_off = (uint32_t)((wc * 32 + l4 * 8 + l7) * RB + l3 * 16)
                           + (uint32_t)APLANES * MB;

    for (int t = 0; t < NT; ++t) {
        // 1) this thread's tile-t load complete (only pending group)
        cp_wait<0>();
        // 2) publish ALL threads' tile-t data; buffer (t+1)&1 reads done
        __syncthreads();
        // 3) prefetch tile t+1 (overlaps with compute below)
        if (t + 1 < NT) load_stage(t + 1);

        const uint32_t stage = sb + (t & 1) * STAGE;
#pragma unroll
        for (int ks = 0; ks < KS; ++ks) {
            const uint32_t kb = (uint32_t)(ks * 32);

            uint32_t bh[8], bl[8];
#pragma unroll
            for (int g = 0; g < 2; ++g) {
                const uint32_t ba = stage + b_off + g * 16 * RB + kb;
                ldm4(bh + 4 * g, ba);
                if (BPLANES == 2) ldm4(bl + 4 * g, ba + MB);
            }
            uint32_t ah[16], al[16];
#pragma unroll
            for (int mf = 0; mf < 4; ++mf) {
                const uint32_t aa = stage + a_off + mf * 16 * RB + kb;
                ldm4(ah + 4 * mf, aa);
                if (APLANES == 2) ldm4(al + 4 * mf, aa + MB);
            }

#pragma unroll
            for (int mf = 0; mf < 4; ++mf)
#pragma unroll
                for (int nf = 0; nf < 4; ++nf)
                    mma16816(acc[mf][nf], ah + 4 * mf, bh + 2 * nf);
            if (BPLANES == 2) {
#pragma unroll
                for (int mf = 0; mf < 4; ++mf)
#pragma unroll
                    for (int nf = 0; nf < 4; ++nf)
                        mma16816(acc[mf][nf], ah + 4 * mf, bl + 2 * nf);
            }
            if (APLANES == 2) {
#pragma unroll
                for (int mf = 0; mf < 4; ++mf)
#pragma unroll
                    for (int nf = 0; nf < 4; ++nf)
                        mma16816(acc[mf][nf], al + 4 * mf, bh + 2 * nf);
            }
        }
    }

    // epilogue: direct gmem stores, float2 per fragment half
    const int q  = lane >> 2;
    const int tq = lane & 3;
    float* C = pC + (size_t)bz * sC;
#pragma unroll
    for (int mf = 0; mf < 4; ++mf) {
        const int m0 = brow + wr * 64 + mf * 16 + q;
#pragma unroll
        for (int nf = 0; nf < 4; ++nf) {
            const int n = bcol + wc * 32 + nf * 8 + 2 * tq;
            *(float2*)(C + (size_t)m0 * ldc + n) =
                make_float2(acc[mf][nf][0], acc[mf][nf][1]);
            *(float2*)(C + (size_t)(m0 + 8) * ldc + n) =
                make_float2(acc[mf][nf][2], acc[mf][nf][3]);
        }
    }
}

// ---------------------------------------------------------------------------
// Q -> (Qh, Ql) elementwise fp16 hi/lo split, 8 elems/thread
// ---------------------------------------------------------------------------
__global__ __launch_bounds__(256)
void cvt_hilo8(const float* __restrict__ x,
               __half* __restrict__ h, __half* __restrict__ l)
{
    const size_t i = ((size_t)blockIdx.x * blockDim.x + threadIdx.x) * 8;
    const float4 a = *(const float4*)(x + i);
    const float4 b = *(const float4*)(x + i + 4);
    const float v[8] = {a.x, a.y, a.z, a.w, b.x, b.y, b.z, b.w};
    float hf[8], lf[8];
#pragma unroll
    for (int j = 0; j < 8; ++j) {
        hf[j] = __half2float(__float2half_rn(v[j]));
        lf[j] = v[j] - hf[j];
    }
    *(uint4*)(h + i) = make_uint4(pk_h2(hf[0], hf[1]), pk_h2(hf[2], hf[3]),
                                  pk_h2(hf[4], hf[5]), pk_h2(hf[6], hf[7]));
    *(uint4*)(l + i) = make_uint4(pk_h2(lf[0], lf[1]), pk_h2(lf[2], lf[3]),
                                  pk_h2(lf[4], lf[5]), pk_h2(lf[6], lf[7]));
}

// ---------------------------------------------------------------------------
// V -> (Vh, Vl) and transposed hi plane (VTh), fp16. 32x32 tiles, block (32,8).
// ---------------------------------------------------------------------------
__global__ __launch_bounds__(256)
void cvtV(const float* __restrict__ V,
          __half* __restrict__ Vh, __half* __restrict__ Vl,
          __half* __restrict__ VTh)
{
    __shared__ float ts[32][33];
    const int bz = blockIdx.z;
    const float* Vb = V + (size_t)bz * LK * DDIM;
    const int x  = blockIdx.x * 32 + threadIdx.x;   // d
    const int y0 = blockIdx.y * 32 + threadIdx.y;   // k base

#pragma unroll
    for (int j = 0; j < 4; ++j) {
        const int k = y0 + j * 8;
        const float v = Vb[(size_t)k * DDIM + x];
        ts[threadIdx.y + j * 8][threadIdx.x] = v;
        const __half hb = __float2half_rn(v);
        const float hfv = __half2float(hb);
        const size_t o = (size_t)bz * LK * DDIM + (size_t)k * DDIM + x;
        Vh[o] = hb;
        Vl[o] = __float2half_rn(v - hfv);
    }
    __syncthreads();
#pragma unroll
    for (int j = 0; j < 4; ++j) {
        const int d = blockIdx.x * 32 + threadIdx.y + j * 8;
        const int k = blockIdx.y * 32 + threadIdx.x;
        const float v = ts[threadIdx.x][threadIdx.y + j * 8];
        const size_t o = (size_t)bz * DDIM * LK + (size_t)d * LK + k;
        VTh[o] = __float2half_rn(v);
    }
}

// ---------------------------------------------------------------------------
// Row softmax in place + emit fp16 plane of the result (single plane).
// ---------------------------------------------------------------------------
__global__ __launch_bounds__(256)
void softmax_rows(float* __restrict__ S, __half* __restrict__ Ph)
{
    __shared__ float redmax[8];
    __shared__ float redsum[8];

    const size_t rowbase = (size_t)blockIdx.x * LK;
    float* p = S + rowbase;
    const int tid  = threadIdx.x;
    const int lane = tid & 31;
    const int warp = tid >> 5;

    const float4 v0 = *(const float4*)(p + tid * 8);
    const float4 v1 = *(const float4*)(p + tid * 8 + 4);

    float m = fmaxf(fmaxf(fmaxf(v0.x, v0.y), fmaxf(v0.z, v0.w)),
                    fmaxf(fmaxf(v1.x, v1.y), fmaxf(v1.z, v1.w)));
#pragma unroll
    for (int o = 16; o > 0; o >>= 1)
        m = fmaxf(m, __shfl_xor_sync(0xffffffffu, m, o));
    if (lane == 0) redmax[warp] = m;
    __syncthreads();
    float bm = redmax[0];
#pragma unroll
    for (int w = 1; w < 8; ++w) bm = fmaxf(bm, redmax[w]);

    float e[8];
    e[0] = __expf(v0.x - bm); e[1] = __expf(v0.y - bm);
    e[2] = __expf(v0.z - bm); e[3] = __expf(v0.w - bm);
    e[4] = __expf(v1.x - bm); e[5] = __expf(v1.y - bm);
    e[6] = __expf(v1.z - bm); e[7] = __expf(v1.w - bm);

    float s = ((e[0] + e[1]) + (e[2] + e[3])) + ((e[4] + e[5]) + (e[6] + e[7]));
#pragma unroll
    for (int o = 16; o > 0; o >>= 1)
        s += __shfl_xor_sync(0xffffffffu, s, o);
    if (lane == 0) redsum[warp] = s;
    __syncthreads();
    float total = redsum[0];
#pragma unroll
    for (int w = 1; w < 8; ++w) total += redsum[w];
    const float inv = 1.0f / total;

    float y[8];
#pragma unroll
    for (int j = 0; j < 8; ++j) y[j] = e[j] * inv;

    *(float4*)(p + tid * 8)     = make_float4(y[0], y[1], y[2], y[3]);
    *(float4*)(p + tid * 8 + 4) = make_float4(y[4], y[5], y[6], y[7]);

    const size_t ob = rowbase + (size_t)tid * 8;
    *(uint4*)(Ph + ob) = make_uint4(pk_h2(y[0], y[1]), pk_h2(y[2], y[3]),
                                    pk_h2(y[4], y[5]), pk_h2(y[6], y[7]));
}

// ---------------------------------------------------------------------------
// kernel_launch
// ---------------------------------------------------------------------------
extern "C" void kernel_launch(void* const* d_in, const int* in_sizes, int n_in,
                              void* d_out, int out_size)
{
    const float* Q = (const float*)d_in[0];
    const float* V = (const float*)d_in[1];
    float* ctx  = (float*)d_out;
    float* attn = ctx + (size_t)BATCH * LQ * DDIM;

    void *qh, *ql, *vh, *vl, *vth, *ph;
    cudaGetSymbolAddress(&qh, g_Qh);
    cudaGetSymbolAddress(&ql, g_Ql);
    cudaGetSymbolAddress(&vh, g_Vh);
    cudaGetSymbolAddress(&vl, g_Vl);
    cudaGetSymbolAddress(&vth, g_VTh);
    cudaGetSymbolAddress(&ph, g_Ph);

    constexpr int SMEM_G1 = NSTAGE * 4 * 128 * 80;    // 81920
    constexpr int SMEM_G2 = NSTAGE * 2 * 128 * 144;   // 73728

    cudaFuncSetAttribute((const void*)gemm_hmma<2, 2, 32, 80>,
                         cudaFuncAttributeMaxDynamicSharedMemorySize, SMEM_G1);
    cudaFuncSetAttribute((const void*)gemm_hmma<1, 1, 64, 144>,
                         cudaFuncAttributeMaxDynamicSharedMemorySize, SMEM_G2);

    // fp16 hi/lo splits
    cvt_hilo8<<<(unsigned)((size_t)BATCH * LQ * DDIM / (256 * 8)), 256>>>(
        Q, (__half*)qh, (__half*)ql);
    cvtV<<<dim3(DDIM / 32, LK / 32, BATCH), dim3(32, 8)>>>(
        V, (__half*)vh, (__half*)vl, (__half*)vth);

    // GEMM1: scores = Q · V^T  (3 MMAs/frag, KT=32) -> attn buffer
    gemm_hmma<2, 2, 32, 80><<<dim3(LK / 128, LQ / 128, BATCH), 256, SMEM_G1>>>(
        (const __half*)qh, (const __half*)ql,
        (const __half*)vh, (const __half*)vl,
        attn, DDIM, LK,
        (long)LQ * DDIM, (long)LK * DDIM, (long)LQ * LK);

    // softmax over key axis (in place) + fp16 P plane
    softmax_rows<<<BATCH * LQ, 256>>>(attn, (__half*)ph);

    // GEMM2: ctx = Ph · VTh^T  (1 MMA/frag, KT=64 — half the sync points)
    gemm_hmma<1, 1, 64, 144><<<dim3(DDIM / 128, LQ / 128, BATCH), 256, SMEM_G2>>>(
        (const __half*)ph, nullptr,
        (const __half*)vth, nullptr,
        ctx, LK, DDIM,
        (long)LQ * LK, (long)DDIM * LK, (long)LQ * DDIM);
}